// round 7
// baseline (speedup 1.0000x reference)
#include <cuda_runtime.h>
#include <cuda_bf16.h>
#include <float.h>

// {scale, 1/scale} computed by the prologue.
__device__ float2 g_scale2;

// ---------------------------------------------------------------------------
// Kernel 1: scale-only prologue. max|W| over [4,2048] -> scale = max/7.
// 1024 threads, 2 float4 loads each. Pure latency chain.
// ---------------------------------------------------------------------------
__global__ void __launch_bounds__(1024)
scale_kernel(const float* __restrict__ W) {
    __shared__ float s_warp[32];
    const int t = threadIdx.x;

    const float4* __restrict__ W4 = reinterpret_cast<const float4*>(W);
    const float4 a = W4[t];
    const float4 b = W4[t + 1024];
    float m = fmaxf(fmaxf(fmaxf(fabsf(a.x), fabsf(a.y)),
                          fmaxf(fabsf(a.z), fabsf(a.w))),
                    fmaxf(fmaxf(fabsf(b.x), fabsf(b.y)),
                          fmaxf(fabsf(b.z), fabsf(b.w))));
    #pragma unroll
    for (int off = 16; off > 0; off >>= 1)
        m = fmaxf(m, __shfl_xor_sync(0xFFFFFFFFu, m, off));
    if ((t & 31) == 0) s_warp[t >> 5] = m;
    __syncthreads();
    if (t == 0) {
        float mm = s_warp[0];
        #pragma unroll
        for (int w = 1; w < 32; w++) mm = fmaxf(mm, s_warp[w]);
        const float scale = mm / 7.0f;
        g_scale2 = make_float2(scale, 1.0f / scale);
    }
}

// ---------------------------------------------------------------------------
// Kernel 2: fused MaxPool3d(2) + inline int4-dequant linear(2048->4) + bias
// + softmax. FOUR batch rows per block (256 threads). Each k-iter handles
// one feature-pair for all 4 rows, structured as two row-pairs so live load
// registers stay at 8 float4 while weights (dequantized inline once) are
// shared across all 4 rows.
//
// x layout: [B, C=4, D=16, H=16, W=16] f32, 16384 floats per row.
// pair index fp in [0,1024): c = fp>>8, rem = fp&255,
//   pd = rem>>5, ph = (rem>>2)&7, pwp = rem&3
// base float offset = c*4096 + pd*512 + ph*32 + pwp*4
// ---------------------------------------------------------------------------
__global__ void __launch_bounds__(256)
fused_pool_linear_softmax_kernel(const float* __restrict__ x,
                                 const float* __restrict__ W,
                                 const float* __restrict__ bias,
                                 float* __restrict__ out) {
    __shared__ float s_red[8][16];   // [warp][row r accs at 4r..4r+3]

    const int b0 = blockIdx.x * 4;
    const int t = threadIdx.x;
    const float* __restrict__ xb0 = x + (size_t)b0 * 16384;
    const float* __restrict__ xb1 = xb0 + 16384;
    const float* __restrict__ xb2 = xb0 + 32768;
    const float* __restrict__ xb3 = xb0 + 49152;

    const float2 sc = g_scale2;            // 8B broadcast, no barrier
    const float scale = sc.x, inv_scale = sc.y;
    const float4 bias4 = *reinterpret_cast<const float4*>(bias);

    float acc[16];
    #pragma unroll
    for (int i = 0; i < 16; i++) acc[i] = 0.0f;

    #pragma unroll
    for (int k = 0; k < 4; k++) {
        const int fp  = t + k * 256;
        const int c   = fp >> 8;
        const int rem = fp & 255;
        const int pd  = rem >> 5;
        const int ph  = (rem >> 2) & 7;
        const int pwp = rem & 3;
        const int off = c * 4096 + pd * 512 + ph * 32 + pwp * 4;

        // weights: load raw, dequant inline once, reuse for all 4 rows
        const int f2 = fp * 2;
        float2 w0 = *reinterpret_cast<const float2*>(&W[f2]);
        float2 w1 = *reinterpret_cast<const float2*>(&W[2048 + f2]);
        float2 w2 = *reinterpret_cast<const float2*>(&W[4096 + f2]);
        float2 w3 = *reinterpret_cast<const float2*>(&W[6144 + f2]);
        w0.x = rintf(w0.x * inv_scale) * scale;
        w0.y = rintf(w0.y * inv_scale) * scale;
        w1.x = rintf(w1.x * inv_scale) * scale;
        w1.y = rintf(w1.y * inv_scale) * scale;
        w2.x = rintf(w2.x * inv_scale) * scale;
        w2.y = rintf(w2.y * inv_scale) * scale;
        w3.x = rintf(w3.x * inv_scale) * scale;
        w3.y = rintf(w3.y * inv_scale) * scale;

        // ---- row pair 0/1 ----
        {
            const float4* pa = reinterpret_cast<const float4*>(xb0 + off);
            const float4* pb = reinterpret_cast<const float4*>(xb1 + off);
            const float4 a0 = __ldcs(pa);
            const float4 a1 = __ldcs(pa + 4);
            const float4 a2 = __ldcs(pa + 64);
            const float4 a3 = __ldcs(pa + 68);
            const float4 c0 = __ldcs(pb);
            const float4 c1 = __ldcs(pb + 4);
            const float4 c2 = __ldcs(pb + 64);
            const float4 c3 = __ldcs(pb + 68);

            const float ma0 = fmaxf(fmaxf(fmaxf(a0.x, a0.y), fmaxf(a1.x, a1.y)),
                                    fmaxf(fmaxf(a2.x, a2.y), fmaxf(a3.x, a3.y)));
            const float ma1 = fmaxf(fmaxf(fmaxf(a0.z, a0.w), fmaxf(a1.z, a1.w)),
                                    fmaxf(fmaxf(a2.z, a2.w), fmaxf(a3.z, a3.w)));
            const float mb0 = fmaxf(fmaxf(fmaxf(c0.x, c0.y), fmaxf(c1.x, c1.y)),
                                    fmaxf(fmaxf(c2.x, c2.y), fmaxf(c3.x, c3.y)));
            const float mb1 = fmaxf(fmaxf(fmaxf(c0.z, c0.w), fmaxf(c1.z, c1.w)),
                                    fmaxf(fmaxf(c2.z, c2.w), fmaxf(c3.z, c3.w)));

            acc[0]  = fmaf(ma0, w0.x, fmaf(ma1, w0.y, acc[0]));
            acc[1]  = fmaf(ma0, w1.x, fmaf(ma1, w1.y, acc[1]));
            acc[2]  = fmaf(ma0, w2.x, fmaf(ma1, w2.y, acc[2]));
            acc[3]  = fmaf(ma0, w3.x, fmaf(ma1, w3.y, acc[3]));
            acc[4]  = fmaf(mb0, w0.x, fmaf(mb1, w0.y, acc[4]));
            acc[5]  = fmaf(mb0, w1.x, fmaf(mb1, w1.y, acc[5]));
            acc[6]  = fmaf(mb0, w2.x, fmaf(mb1, w2.y, acc[6]));
            acc[7]  = fmaf(mb0, w3.x, fmaf(mb1, w3.y, acc[7]));
        }
        // ---- row pair 2/3 ----
        {
            const float4* pa = reinterpret_cast<const float4*>(xb2 + off);
            const float4* pb = reinterpret_cast<const float4*>(xb3 + off);
            const float4 a0 = __ldcs(pa);
            const float4 a1 = __ldcs(pa + 4);
            const float4 a2 = __ldcs(pa + 64);
            const float4 a3 = __ldcs(pa + 68);
            const float4 c0 = __ldcs(pb);
            const float4 c1 = __ldcs(pb + 4);
            const float4 c2 = __ldcs(pb + 64);
            const float4 c3 = __ldcs(pb + 68);

            const float ma0 = fmaxf(fmaxf(fmaxf(a0.x, a0.y), fmaxf(a1.x, a1.y)),
                                    fmaxf(fmaxf(a2.x, a2.y), fmaxf(a3.x, a3.y)));
            const float ma1 = fmaxf(fmaxf(fmaxf(a0.z, a0.w), fmaxf(a1.z, a1.w)),
                                    fmaxf(fmaxf(a2.z, a2.w), fmaxf(a3.z, a3.w)));
            const float mb0 = fmaxf(fmaxf(fmaxf(c0.x, c0.y), fmaxf(c1.x, c1.y)),
                                    fmaxf(fmaxf(c2.x, c2.y), fmaxf(c3.x, c3.y)));
            const float mb1 = fmaxf(fmaxf(fmaxf(c0.z, c0.w), fmaxf(c1.z, c1.w)),
                                    fmaxf(fmaxf(c2.z, c2.w), fmaxf(c3.z, c3.w)));

            acc[8]  = fmaf(ma0, w0.x, fmaf(ma1, w0.y, acc[8]));
            acc[9]  = fmaf(ma0, w1.x, fmaf(ma1, w1.y, acc[9]));
            acc[10] = fmaf(ma0, w2.x, fmaf(ma1, w2.y, acc[10]));
            acc[11] = fmaf(ma0, w3.x, fmaf(ma1, w3.y, acc[11]));
            acc[12] = fmaf(mb0, w0.x, fmaf(mb1, w0.y, acc[12]));
            acc[13] = fmaf(mb0, w1.x, fmaf(mb1, w1.y, acc[13]));
            acc[14] = fmaf(mb0, w2.x, fmaf(mb1, w2.y, acc[14]));
            acc[15] = fmaf(mb0, w3.x, fmaf(mb1, w3.y, acc[15]));
        }
    }

    // warp reduce all 16 accumulators
    #pragma unroll
    for (int off = 16; off > 0; off >>= 1) {
        #pragma unroll
        for (int i = 0; i < 16; i++)
            acc[i] += __shfl_xor_sync(0xFFFFFFFFu, acc[i], off);
    }
    const int wid = t >> 5;
    if ((t & 31) == 0) {
        #pragma unroll
        for (int i = 0; i < 16; i++) s_red[wid][i] = acc[i];
    }
    __syncthreads();

    // threads 0..3 each finish one row
    if (t < 4) {
        const int base = t * 4;
        float l0 = bias4.x, l1 = bias4.y, l2 = bias4.z, l3 = bias4.w;
        #pragma unroll
        for (int w = 0; w < 8; w++) {
            l0 += s_red[w][base + 0];
            l1 += s_red[w][base + 1];
            l2 += s_red[w][base + 2];
            l3 += s_red[w][base + 3];
        }
        const float mx = fmaxf(fmaxf(l0, l1), fmaxf(l2, l3));
        const float e0 = __expf(l0 - mx);
        const float e1 = __expf(l1 - mx);
        const float e2 = __expf(l2 - mx);
        const float e3 = __expf(l3 - mx);
        const float inv = 1.0f / (e0 + e1 + e2 + e3);
        float4 r = make_float4(e0 * inv, e1 * inv, e2 * inv, e3 * inv);
        *reinterpret_cast<float4*>(out + (size_t)(b0 + t) * 4) = r;
    }
}

extern "C" void kernel_launch(void* const* d_in, const int* in_sizes, int n_in,
                              void* d_out, int out_size) {
    const float* x = (const float*)d_in[0];   // [8192,4,16,16,16]
    const float* W = (const float*)d_in[1];   // [4,2048]
    const float* b = (const float*)d_in[2];   // [4]
    float* out = (float*)d_out;               // [8192,4]

    scale_kernel<<<1, 1024>>>(W);
    fused_pool_linear_softmax_kernel<<<2048, 256>>>(x, W, b, out);
}

// round 8
// speedup vs baseline: 1.0388x; 1.0388x over previous
#include <cuda_runtime.h>
#include <cuda_bf16.h>
#include <float.h>

// Packed {scale (lo 32b), 1/scale (hi 32b)}. Zero means "not yet published".
// scale > 0 always, so the published value is never 0 — the value is its own
// ready flag. 64-bit accesses are single atomic LDG.64/STG.64.
__device__ volatile unsigned long long g_scale_packed;

// ---------------------------------------------------------------------------
// Single fused kernel, grid 4097:
//   block 0     : compute scale = max|W|/7, publish packed {s, 1/s}.
//   blocks 1..N : MaxPool3d(2) + inline int4-dequant linear(2048->4) + bias
//                 + softmax, 2 batch rows per block (R6 body, measured
//                 81.2us / 84% DRAM). Each spins on ONE volatile 64-bit L2
//                 load before its first FMA (wave 1 only; later waves see it
//                 set immediately).
//
// x layout: [B, C=4, D=16, H=16, W=16] f32, 16384 floats per row.
// pair index fp in [0,1024): c = fp>>8, rem = fp&255,
//   pd = rem>>5, ph = (rem>>2)&7, pwp = rem&3
// base float offset = c*4096 + pd*512 + ph*32 + pwp*4
// ---------------------------------------------------------------------------
__global__ void __launch_bounds__(256)
fused_pool_linear_softmax_kernel(const float* __restrict__ x,
                                 const float* __restrict__ W,
                                 const float* __restrict__ bias,
                                 float* __restrict__ out) {
    const int t = threadIdx.x;

    // ---------------- block 0: scale producer ----------------
    if (blockIdx.x == 0) {
        __shared__ float s_warp[8];
        const float4* __restrict__ W4 = reinterpret_cast<const float4*>(W);
        float m = 0.0f;
        #pragma unroll
        for (int k = 0; k < 8; k++) {
            const float4 w = W4[t + k * 256];
            m = fmaxf(m, fmaxf(fmaxf(fabsf(w.x), fabsf(w.y)),
                               fmaxf(fabsf(w.z), fabsf(w.w))));
        }
        #pragma unroll
        for (int off = 16; off > 0; off >>= 1)
            m = fmaxf(m, __shfl_xor_sync(0xFFFFFFFFu, m, off));
        if ((t & 31) == 0) s_warp[t >> 5] = m;
        __syncthreads();
        if (t == 0) {
            float mm = fmaxf(fmaxf(fmaxf(s_warp[0], s_warp[1]),
                                   fmaxf(s_warp[2], s_warp[3])),
                             fmaxf(fmaxf(s_warp[4], s_warp[5]),
                                   fmaxf(s_warp[6], s_warp[7])));
            const float scale = mm / 7.0f;
            const float inv_scale = 1.0f / scale;
            const unsigned long long packed =
                ((unsigned long long)__float_as_uint(inv_scale) << 32) |
                (unsigned long long)__float_as_uint(scale);
            g_scale_packed = packed;   // volatile 64-bit store: flag == data
        }
        return;
    }

    // ---------------- blocks 1..4096: main body ----------------
    __shared__ float s_red[8][8];   // [warp][row0 accs 0..3 | row1 accs 4..7]

    const int b0 = (blockIdx.x - 1) * 2;
    const float* __restrict__ xb0 = x + (size_t)b0 * 16384;
    const float* __restrict__ xb1 = xb0 + 16384;

    const float4 bias4 = *reinterpret_cast<const float4*>(bias);

    // Spin for the packed scale (one L2 load when already published).
    unsigned long long v = g_scale_packed;
    while (v == 0ull) v = g_scale_packed;
    const float scale     = __uint_as_float((unsigned int)v);
    const float inv_scale = __uint_as_float((unsigned int)(v >> 32));

    float p0 = 0.0f, p1 = 0.0f, p2 = 0.0f, p3 = 0.0f;   // row 0 partials
    float q0 = 0.0f, q1 = 0.0f, q2 = 0.0f, q3 = 0.0f;   // row 1 partials

    #pragma unroll
    for (int k = 0; k < 4; k++) {
        const int fp  = t + k * 256;
        const int c   = fp >> 8;
        const int rem = fp & 255;
        const int pd  = rem >> 5;
        const int ph  = (rem >> 2) & 7;
        const int pwp = rem & 3;
        const int off = c * 4096 + pd * 512 + ph * 32 + pwp * 4;

        const float4* pa = reinterpret_cast<const float4*>(xb0 + off);
        const float4* pb = reinterpret_cast<const float4*>(xb1 + off);

        const float4 a0 = __ldcs(pa);        // (d0, h0)
        const float4 a1 = __ldcs(pa + 4);    // (d0, h1)
        const float4 a2 = __ldcs(pa + 64);   // (d1, h0)
        const float4 a3 = __ldcs(pa + 68);   // (d1, h1)
        const float4 c0 = __ldcs(pb);
        const float4 c1 = __ldcs(pb + 4);
        const float4 c2 = __ldcs(pb + 64);
        const float4 c3 = __ldcs(pb + 68);

        const float ma0 = fmaxf(fmaxf(fmaxf(a0.x, a0.y), fmaxf(a1.x, a1.y)),
                                fmaxf(fmaxf(a2.x, a2.y), fmaxf(a3.x, a3.y)));
        const float ma1 = fmaxf(fmaxf(fmaxf(a0.z, a0.w), fmaxf(a1.z, a1.w)),
                                fmaxf(fmaxf(a2.z, a2.w), fmaxf(a3.z, a3.w)));
        const float mb0 = fmaxf(fmaxf(fmaxf(c0.x, c0.y), fmaxf(c1.x, c1.y)),
                                fmaxf(fmaxf(c2.x, c2.y), fmaxf(c3.x, c3.y)));
        const float mb1 = fmaxf(fmaxf(fmaxf(c0.z, c0.w), fmaxf(c1.z, c1.w)),
                                fmaxf(fmaxf(c2.z, c2.w), fmaxf(c3.z, c3.w)));

        const int f2 = fp * 2;
        float2 w0 = *reinterpret_cast<const float2*>(&W[f2]);
        float2 w1 = *reinterpret_cast<const float2*>(&W[2048 + f2]);
        float2 w2 = *reinterpret_cast<const float2*>(&W[4096 + f2]);
        float2 w3 = *reinterpret_cast<const float2*>(&W[6144 + f2]);

        // inline int4 dequant (half-to-even; clip(-8,7) never binds)
        w0.x = rintf(w0.x * inv_scale) * scale;
        w0.y = rintf(w0.y * inv_scale) * scale;
        w1.x = rintf(w1.x * inv_scale) * scale;
        w1.y = rintf(w1.y * inv_scale) * scale;
        w2.x = rintf(w2.x * inv_scale) * scale;
        w2.y = rintf(w2.y * inv_scale) * scale;
        w3.x = rintf(w3.x * inv_scale) * scale;
        w3.y = rintf(w3.y * inv_scale) * scale;

        p0 = fmaf(ma0, w0.x, fmaf(ma1, w0.y, p0));
        p1 = fmaf(ma0, w1.x, fmaf(ma1, w1.y, p1));
        p2 = fmaf(ma0, w2.x, fmaf(ma1, w2.y, p2));
        p3 = fmaf(ma0, w3.x, fmaf(ma1, w3.y, p3));
        q0 = fmaf(mb0, w0.x, fmaf(mb1, w0.y, q0));
        q1 = fmaf(mb0, w1.x, fmaf(mb1, w1.y, q1));
        q2 = fmaf(mb0, w2.x, fmaf(mb1, w2.y, q2));
        q3 = fmaf(mb0, w3.x, fmaf(mb1, w3.y, q3));
    }

    // warp reduce all 8 accumulators
    #pragma unroll
    for (int off = 16; off > 0; off >>= 1) {
        p0 += __shfl_xor_sync(0xFFFFFFFFu, p0, off);
        p1 += __shfl_xor_sync(0xFFFFFFFFu, p1, off);
        p2 += __shfl_xor_sync(0xFFFFFFFFu, p2, off);
        p3 += __shfl_xor_sync(0xFFFFFFFFu, p3, off);
        q0 += __shfl_xor_sync(0xFFFFFFFFu, q0, off);
        q1 += __shfl_xor_sync(0xFFFFFFFFu, q1, off);
        q2 += __shfl_xor_sync(0xFFFFFFFFu, q2, off);
        q3 += __shfl_xor_sync(0xFFFFFFFFu, q3, off);
    }
    const int wid = t >> 5;
    if ((t & 31) == 0) {
        s_red[wid][0] = p0;  s_red[wid][1] = p1;
        s_red[wid][2] = p2;  s_red[wid][3] = p3;
        s_red[wid][4] = q0;  s_red[wid][5] = q1;
        s_red[wid][6] = q2;  s_red[wid][7] = q3;
    }
    __syncthreads();

    // threads 0 and 1 each finish one row
    if (t < 2) {
        const int base = t * 4;
        float l0 = bias4.x, l1 = bias4.y, l2 = bias4.z, l3 = bias4.w;
        #pragma unroll
        for (int w = 0; w < 8; w++) {
            l0 += s_red[w][base + 0];
            l1 += s_red[w][base + 1];
            l2 += s_red[w][base + 2];
            l3 += s_red[w][base + 3];
        }
        const float mx = fmaxf(fmaxf(l0, l1), fmaxf(l2, l3));
        const float e0 = __expf(l0 - mx);
        const float e1 = __expf(l1 - mx);
        const float e2 = __expf(l2 - mx);
        const float e3 = __expf(l3 - mx);
        const float inv = 1.0f / (e0 + e1 + e2 + e3);
        float4 r = make_float4(e0 * inv, e1 * inv, e2 * inv, e3 * inv);
        *reinterpret_cast<float4*>(out + (size_t)(b0 + t) * 4) = r;
    }
}

extern "C" void kernel_launch(void* const* d_in, const int* in_sizes, int n_in,
                              void* d_out, int out_size) {
    const float* x = (const float*)d_in[0];   // [8192,4,16,16,16]
    const float* W = (const float*)d_in[1];   // [4,2048]
    const float* b = (const float*)d_in[2];   // [4]
    float* out = (float*)d_out;               // [8192,4]

    fused_pool_linear_softmax_kernel<<<4097, 256>>>(x, W, b, out);
}

// round 9
// speedup vs baseline: 1.0554x; 1.0159x over previous
#include <cuda_runtime.h>
#include <cuda_bf16.h>
#include <float.h>

// Packed {scale (lo 32b), 1/scale (hi 32b)}. Zero means "not yet published".
// scale > 0 always, so the published value is never 0 — the value is its own
// ready flag. 64-bit accesses are single atomic LDG.64/STG.64.
__device__ volatile unsigned long long g_scale_packed;

// ---------------------------------------------------------------------------
// Single fused kernel, grid 4097:
//   block 0     : compute scale = max|W|/7, publish packed {s, 1/s}.
//   blocks 1..N : MaxPool3d(2) + inline int4-dequant linear(2048->4) + bias
//                 + softmax, 2 batch rows per block.
// k=0 is software-pipelined: its x loads (8x LDG.128) and raw weight loads
// (4x LDG.64, scale-independent) are issued BEFORE the scale spin, so wave-1
// CTAs stream data while waiting for block 0 to publish.
//
// x layout: [B, C=4, D=16, H=16, W=16] f32, 16384 floats per row.
// pair index fp in [0,1024): c = fp>>8, rem = fp&255,
//   pd = rem>>5, ph = (rem>>2)&7, pwp = rem&3
// base float offset = c*4096 + pd*512 + ph*32 + pwp*4
// ---------------------------------------------------------------------------
__global__ void __launch_bounds__(256)
fused_pool_linear_softmax_kernel(const float* __restrict__ x,
                                 const float* __restrict__ W,
                                 const float* __restrict__ bias,
                                 float* __restrict__ out) {
    const int t = threadIdx.x;

    // ---------------- block 0: scale producer ----------------
    if (blockIdx.x == 0) {
        __shared__ float s_warp[8];
        const float4* __restrict__ W4 = reinterpret_cast<const float4*>(W);
        float m = 0.0f;
        #pragma unroll
        for (int k = 0; k < 8; k++) {
            const float4 w = W4[t + k * 256];
            m = fmaxf(m, fmaxf(fmaxf(fabsf(w.x), fabsf(w.y)),
                               fmaxf(fabsf(w.z), fabsf(w.w))));
        }
        #pragma unroll
        for (int off = 16; off > 0; off >>= 1)
            m = fmaxf(m, __shfl_xor_sync(0xFFFFFFFFu, m, off));
        if ((t & 31) == 0) s_warp[t >> 5] = m;
        __syncthreads();
        if (t == 0) {
            float mm = fmaxf(fmaxf(fmaxf(s_warp[0], s_warp[1]),
                                   fmaxf(s_warp[2], s_warp[3])),
                             fmaxf(fmaxf(s_warp[4], s_warp[5]),
                                   fmaxf(s_warp[6], s_warp[7])));
            const float scale = mm / 7.0f;
            const float inv_scale = 1.0f / scale;
            const unsigned long long packed =
                ((unsigned long long)__float_as_uint(inv_scale) << 32) |
                (unsigned long long)__float_as_uint(scale);
            g_scale_packed = packed;   // volatile 64-bit store: flag == data
        }
        return;
    }

    // ---------------- blocks 1..4096: main body ----------------
    __shared__ float s_red[8][8];   // [warp][row0 accs 0..3 | row1 accs 4..7]

    const int b0 = (blockIdx.x - 1) * 2;
    const float* __restrict__ xb0 = x + (size_t)b0 * 16384;
    const float* __restrict__ xb1 = xb0 + 16384;

    const float4 bias4 = *reinterpret_cast<const float4*>(bias);

    float p0 = 0.0f, p1 = 0.0f, p2 = 0.0f, p3 = 0.0f;   // row 0 partials
    float q0 = 0.0f, q1 = 0.0f, q2 = 0.0f, q3 = 0.0f;   // row 1 partials

    // ===== peeled k=0: issue loads BEFORE the scale spin =====
    const int fp0  = t;
    const int c_0  = fp0 >> 8;
    const int rem0 = fp0 & 255;
    const int off0 = c_0 * 4096 + (rem0 >> 5) * 512 + ((rem0 >> 2) & 7) * 32
                     + (rem0 & 3) * 4;

    const float4* pa0 = reinterpret_cast<const float4*>(xb0 + off0);
    const float4* pb0 = reinterpret_cast<const float4*>(xb1 + off0);
    const float4 Pa0 = __ldcs(pa0);
    const float4 Pa1 = __ldcs(pa0 + 4);
    const float4 Pa2 = __ldcs(pa0 + 64);
    const float4 Pa3 = __ldcs(pa0 + 68);
    const float4 Pc0 = __ldcs(pb0);
    const float4 Pc1 = __ldcs(pb0 + 4);
    const float4 Pc2 = __ldcs(pb0 + 64);
    const float4 Pc3 = __ldcs(pb0 + 68);

    const int pf2 = fp0 * 2;
    float2 Pw0 = *reinterpret_cast<const float2*>(&W[pf2]);
    float2 Pw1 = *reinterpret_cast<const float2*>(&W[2048 + pf2]);
    float2 Pw2 = *reinterpret_cast<const float2*>(&W[4096 + pf2]);
    float2 Pw3 = *reinterpret_cast<const float2*>(&W[6144 + pf2]);

    // Spin for the packed scale; the loads above are in flight meanwhile.
    unsigned long long v = g_scale_packed;
    while (v == 0ull) v = g_scale_packed;
    const float scale     = __uint_as_float((unsigned int)v);
    const float inv_scale = __uint_as_float((unsigned int)(v >> 32));

    // process peeled k=0
    {
        const float ma0 = fmaxf(fmaxf(fmaxf(Pa0.x, Pa0.y), fmaxf(Pa1.x, Pa1.y)),
                                fmaxf(fmaxf(Pa2.x, Pa2.y), fmaxf(Pa3.x, Pa3.y)));
        const float ma1 = fmaxf(fmaxf(fmaxf(Pa0.z, Pa0.w), fmaxf(Pa1.z, Pa1.w)),
                                fmaxf(fmaxf(Pa2.z, Pa2.w), fmaxf(Pa3.z, Pa3.w)));
        const float mb0 = fmaxf(fmaxf(fmaxf(Pc0.x, Pc0.y), fmaxf(Pc1.x, Pc1.y)),
                                fmaxf(fmaxf(Pc2.x, Pc2.y), fmaxf(Pc3.x, Pc3.y)));
        const float mb1 = fmaxf(fmaxf(fmaxf(Pc0.z, Pc0.w), fmaxf(Pc1.z, Pc1.w)),
                                fmaxf(fmaxf(Pc2.z, Pc2.w), fmaxf(Pc3.z, Pc3.w)));

        Pw0.x = rintf(Pw0.x * inv_scale) * scale;
        Pw0.y = rintf(Pw0.y * inv_scale) * scale;
        Pw1.x = rintf(Pw1.x * inv_scale) * scale;
        Pw1.y = rintf(Pw1.y * inv_scale) * scale;
        Pw2.x = rintf(Pw2.x * inv_scale) * scale;
        Pw2.y = rintf(Pw2.y * inv_scale) * scale;
        Pw3.x = rintf(Pw3.x * inv_scale) * scale;
        Pw3.y = rintf(Pw3.y * inv_scale) * scale;

        p0 = fmaf(ma0, Pw0.x, fmaf(ma1, Pw0.y, p0));
        p1 = fmaf(ma0, Pw1.x, fmaf(ma1, Pw1.y, p1));
        p2 = fmaf(ma0, Pw2.x, fmaf(ma1, Pw2.y, p2));
        p3 = fmaf(ma0, Pw3.x, fmaf(ma1, Pw3.y, p3));
        q0 = fmaf(mb0, Pw0.x, fmaf(mb1, Pw0.y, q0));
        q1 = fmaf(mb0, Pw1.x, fmaf(mb1, Pw1.y, q1));
        q2 = fmaf(mb0, Pw2.x, fmaf(mb1, Pw2.y, q2));
        q3 = fmaf(mb0, Pw3.x, fmaf(mb1, Pw3.y, q3));
    }

    // ===== k = 1..3 =====
    #pragma unroll
    for (int k = 1; k < 4; k++) {
        const int fp  = t + k * 256;
        const int c   = fp >> 8;
        const int rem = fp & 255;
        const int pd  = rem >> 5;
        const int ph  = (rem >> 2) & 7;
        const int pwp = rem & 3;
        const int off = c * 4096 + pd * 512 + ph * 32 + pwp * 4;

        const float4* pa = reinterpret_cast<const float4*>(xb0 + off);
        const float4* pb = reinterpret_cast<const float4*>(xb1 + off);

        const float4 a0 = __ldcs(pa);        // (d0, h0)
        const float4 a1 = __ldcs(pa + 4);    // (d0, h1)
        const float4 a2 = __ldcs(pa + 64);   // (d1, h0)
        const float4 a3 = __ldcs(pa + 68);   // (d1, h1)
        const float4 c0 = __ldcs(pb);
        const float4 c1 = __ldcs(pb + 4);
        const float4 c2 = __ldcs(pb + 64);
        const float4 c3 = __ldcs(pb + 68);

        const float ma0 = fmaxf(fmaxf(fmaxf(a0.x, a0.y), fmaxf(a1.x, a1.y)),
                                fmaxf(fmaxf(a2.x, a2.y), fmaxf(a3.x, a3.y)));
        const float ma1 = fmaxf(fmaxf(fmaxf(a0.z, a0.w), fmaxf(a1.z, a1.w)),
                                fmaxf(fmaxf(a2.z, a2.w), fmaxf(a3.z, a3.w)));
        const float mb0 = fmaxf(fmaxf(fmaxf(c0.x, c0.y), fmaxf(c1.x, c1.y)),
                                fmaxf(fmaxf(c2.x, c2.y), fmaxf(c3.x, c3.y)));
        const float mb1 = fmaxf(fmaxf(fmaxf(c0.z, c0.w), fmaxf(c1.z, c1.w)),
                                fmaxf(fmaxf(c2.z, c2.w), fmaxf(c3.z, c3.w)));

        const int f2 = fp * 2;
        float2 w0 = *reinterpret_cast<const float2*>(&W[f2]);
        float2 w1 = *reinterpret_cast<const float2*>(&W[2048 + f2]);
        float2 w2 = *reinterpret_cast<const float2*>(&W[4096 + f2]);
        float2 w3 = *reinterpret_cast<const float2*>(&W[6144 + f2]);

        // inline int4 dequant (half-to-even; clip(-8,7) never binds)
        w0.x = rintf(w0.x * inv_scale) * scale;
        w0.y = rintf(w0.y * inv_scale) * scale;
        w1.x = rintf(w1.x * inv_scale) * scale;
        w1.y = rintf(w1.y * inv_scale) * scale;
        w2.x = rintf(w2.x * inv_scale) * scale;
        w2.y = rintf(w2.y * inv_scale) * scale;
        w3.x = rintf(w3.x * inv_scale) * scale;
        w3.y = rintf(w3.y * inv_scale) * scale;

        p0 = fmaf(ma0, w0.x, fmaf(ma1, w0.y, p0));
        p1 = fmaf(ma0, w1.x, fmaf(ma1, w1.y, p1));
        p2 = fmaf(ma0, w2.x, fmaf(ma1, w2.y, p2));
        p3 = fmaf(ma0, w3.x, fmaf(ma1, w3.y, p3));
        q0 = fmaf(mb0, w0.x, fmaf(mb1, w0.y, q0));
        q1 = fmaf(mb0, w1.x, fmaf(mb1, w1.y, q1));
        q2 = fmaf(mb0, w2.x, fmaf(mb1, w2.y, q2));
        q3 = fmaf(mb0, w3.x, fmaf(mb1, w3.y, q3));
    }

    // warp reduce all 8 accumulators
    #pragma unroll
    for (int off = 16; off > 0; off >>= 1) {
        p0 += __shfl_xor_sync(0xFFFFFFFFu, p0, off);
        p1 += __shfl_xor_sync(0xFFFFFFFFu, p1, off);
        p2 += __shfl_xor_sync(0xFFFFFFFFu, p2, off);
        p3 += __shfl_xor_sync(0xFFFFFFFFu, p3, off);
        q0 += __shfl_xor_sync(0xFFFFFFFFu, q0, off);
        q1 += __shfl_xor_sync(0xFFFFFFFFu, q1, off);
        q2 += __shfl_xor_sync(0xFFFFFFFFu, q2, off);
        q3 += __shfl_xor_sync(0xFFFFFFFFu, q3, off);
    }
    const int wid = t >> 5;
    if ((t & 31) == 0) {
        s_red[wid][0] = p0;  s_red[wid][1] = p1;
        s_red[wid][2] = p2;  s_red[wid][3] = p3;
        s_red[wid][4] = q0;  s_red[wid][5] = q1;
        s_red[wid][6] = q2;  s_red[wid][7] = q3;
    }
    __syncthreads();

    // threads 0 and 1 each finish one row
    if (t < 2) {
        const int base = t * 4;
        float l0 = bias4.x, l1 = bias4.y, l2 = bias4.z, l3 = bias4.w;
        #pragma unroll
        for (int w = 0; w < 8; w++) {
            l0 += s_red[w][base + 0];
            l1 += s_red[w][base + 1];
            l2 += s_red[w][base + 2];
            l3 += s_red[w][base + 3];
        }
        const float mx = fmaxf(fmaxf(l0, l1), fmaxf(l2, l3));
        const float e0 = __expf(l0 - mx);
        const float e1 = __expf(l1 - mx);
        const float e2 = __expf(l2 - mx);
        const float e3 = __expf(l3 - mx);
        const float inv = 1.0f / (e0 + e1 + e2 + e3);
        float4 r = make_float4(e0 * inv, e1 * inv, e2 * inv, e3 * inv);
        *reinterpret_cast<float4*>(out + (size_t)(b0 + t) * 4) = r;
    }
}

extern "C" void kernel_launch(void* const* d_in, const int* in_sizes, int n_in,
                              void* d_out, int out_size) {
    const float* x = (const float*)d_in[0];   // [8192,4,16,16,16]
    const float* W = (const float*)d_in[1];   // [4,2048]
    const float* b = (const float*)d_in[2];   // [4]
    float* out = (float*)d_out;               // [8192,4]

    fused_pool_linear_softmax_kernel<<<4097, 256>>>(x, W, b, out);
}